// round 12
// baseline (speedup 1.0000x reference)
#include <cuda_runtime.h>
#include <cuda_bf16.h>

// ---------------------------------------------------------------------------
// QuantizedLinear: out = x @ quantize(W)^T + bias
// quantize(w) = clamp(ceil(w - 0.5), -4, 3)  (== jnp argmin, first-index ties)
// W = randn*0.1 -> nonzero quantized entries need |w| >= 5 sigma -> nnz ~ 10.
//
// SINGLE persistent kernel, one co-resident wave (grid=148*4, 256 thr, <=64 regs):
//   quant blocks: stream-read W (64 MB), collect nonzeros, signal g_ready.
//   fill blocks:  register-cached bias -> pure STG stream over owned rows
//                 (overlaps with the quant read stream), then spin on g_ready
//                 (quant never waits -> deadlock-free), then apply nnz fixups
//                 to owned rows only (no cross-block races).
//   nnz > NNZ_CAP: fill blocks run an owned-rows dense GEMM (safety net).
//   Last-finishing block resets all counters for the next graph replay.
// ---------------------------------------------------------------------------

#define NNZ_CAP (1 << 20)   // 1M entries = 8 MB scratch
#define ROWS_PB 4           // rows per fill chunk
#define NBLOCKS 592         // 148 SMs * 4 blocks: guaranteed single wave
#define NTHREADS 256

__device__ int                   g_nnz;      // zero-init; reset at end
__device__ unsigned int          g_qdone;    // quant-block completion ticket
__device__ volatile unsigned int g_ready;    // all nonzeros published
__device__ unsigned int          g_done;     // global reset ticket
__device__ unsigned int          g_eidx[NNZ_CAP];   // o*IN + i
__device__ float                 g_eval[NNZ_CAP];   // quantized level

__device__ __forceinline__ float quant1(float w) {
    float q = ceilf(w - 0.5f);               // round-half-down, exact vs argmin
    return fmaxf(-4.0f, fminf(3.0f, q));
}

__global__ void __launch_bounds__(NTHREADS, 4)
k_fused(const float* __restrict__ x,
        const float* __restrict__ weight,
        const float* __restrict__ bias,
        float* __restrict__ out,
        int IN, int OUT, int B, int QB) {
    const int tid = threadIdx.x;

    if ((int)blockIdx.x < QB) {
        // ================= QUANT ROLE: pure-read stream over W ==============
        const unsigned Wn = (unsigned)OUT * (unsigned)IN;
        const unsigned W4 = Wn >> 2;
        const unsigned gid = blockIdx.x * NTHREADS + tid;
        const unsigned stride = (unsigned)QB * NTHREADS;
        const float4* w4p = reinterpret_cast<const float4*>(weight);
        #pragma unroll 4
        for (unsigned t = gid; t < W4; t += stride) {
            float4 w = __ldcs(&w4p[t]);      // streaming: no reuse
            float q0 = quant1(w.x), q1 = quant1(w.y);
            float q2 = quant1(w.z), q3 = quant1(w.w);
            if ((q0 != 0.f) | (q1 != 0.f) | (q2 != 0.f) | (q3 != 0.f)) {
                unsigned base = t << 2;
                if (q0 != 0.f) { int s = atomicAdd(&g_nnz, 1); if (s < NNZ_CAP) { g_eidx[s] = base + 0u; g_eval[s] = q0; } }
                if (q1 != 0.f) { int s = atomicAdd(&g_nnz, 1); if (s < NNZ_CAP) { g_eidx[s] = base + 1u; g_eval[s] = q1; } }
                if (q2 != 0.f) { int s = atomicAdd(&g_nnz, 1); if (s < NNZ_CAP) { g_eidx[s] = base + 2u; g_eval[s] = q2; } }
                if (q3 != 0.f) { int s = atomicAdd(&g_nnz, 1); if (s < NNZ_CAP) { g_eidx[s] = base + 3u; g_eval[s] = q3; } }
            }
        }
        unsigned tail = Wn & 3u;             // no-op for 4-divisible shapes
        if (gid < tail) {
            unsigned e = (W4 << 2) + gid;
            float q = quant1(weight[e]);
            if (q != 0.f) { int s = atomicAdd(&g_nnz, 1); if (s < NNZ_CAP) { g_eidx[s] = e; g_eval[s] = q; } }
        }
        __threadfence();                     // publish g_eidx/g_eval stores
        __syncthreads();
        if (tid == 0) {
            unsigned t = atomicAdd(&g_qdone, 1u);
            if (t == (unsigned)QB - 1u) atomicExch((unsigned int*)&g_ready, 1u);
        }
    } else {
        // ================= FILL ROLE: owned rows ============================
        const int fb = blockIdx.x - QB;                 // fill-block id
        const int FB = NBLOCKS - QB;
        const int nchunks = (B + ROWS_PB - 1) / ROWS_PB;

        // ---- Phase A: bias fill (pure-store stream, bias in registers) ----
        const unsigned OUT4 = (unsigned)OUT >> 2;
        const int cpt = (int)(OUT4 / NTHREADS);         // float4 cols / thread
        const bool fast = ((OUT & 3) == 0) && (OUT4 % NTHREADS == 0) && cpt <= 8;
        if (fast) {
            float4 bc[8];
            const float4* b4 = reinterpret_cast<const float4*>(bias);
            #pragma unroll
            for (int c = 0; c < 8; c++)
                if (c < cpt) bc[c] = __ldg(&b4[tid + c * NTHREADS]);
            float4* o4 = reinterpret_cast<float4*>(out);
            for (int ch = fb; ch < nchunks; ch += FB) {
                const int r0 = ch * ROWS_PB;
                const int nr = min(ROWS_PB, B - r0);
                for (int r = 0; r < nr; r++) {
                    float4* row = o4 + (size_t)(r0 + r) * OUT4;
                    #pragma unroll
                    for (int c = 0; c < 8; c++)
                        if (c < cpt) __stcs(&row[tid + c * NTHREADS], bc[c]);
                }
            }
        } else {                                        // generic scalar path
            for (int ch = fb; ch < nchunks; ch += FB) {
                const int r0 = ch * ROWS_PB;
                const unsigned n = (unsigned)min(ROWS_PB, B - r0) * (unsigned)OUT;
                float* ob = out + (size_t)r0 * OUT;
                for (unsigned t = tid; t < n; t += NTHREADS)
                    ob[t] = __ldg(&bias[t % (unsigned)OUT]);
            }
        }
        __syncthreads();                    // fill stores visible block-wide

        // ---- wait for quant side (quant never waits -> no deadlock;
        //      all NBLOCKS co-resident by construction, single wave) ----
        if (tid == 0) { while (g_ready == 0u) { } }
        __syncthreads();
        __threadfence();                    // acquire published entries
        const int nnz = *((volatile int*)&g_nnz);

        if (nnz <= NNZ_CAP) {
            // ---- Phase B: fixups on owned rows only ----
            if (nnz > 0) {
                for (int ch = fb; ch < nchunks; ch += FB) {
                    const int r0 = ch * ROWS_PB;
                    const int nr = min(ROWS_PB, B - r0);
                    const int items = nnz * nr;
                    for (int t = tid; t < items; t += NTHREADS) {
                        const int e = t / nr;
                        const int r = t - e * nr;
                        const unsigned idx = __ldg(&g_eidx[e]);
                        const float v = __ldg(&g_eval[e]);
                        const unsigned o = idx / (unsigned)IN;  // shifts (pow2)
                        const unsigned i = idx % (unsigned)IN;
                        const int b = r0 + r;
                        atomicAdd(&out[(size_t)b * OUT + o],
                                  v * __ldg(&x[(size_t)b * IN + i]));
                    }
                }
            }
        } else {
            // ---- Dense safety net: owned-rows GEMM (never taken) ----
            __shared__ float xs[ROWS_PB][1024];
            for (int ch = fb; ch < nchunks; ch += FB) {
                const int r0 = ch * ROWS_PB;
                const int nr = min(ROWS_PB, B - r0);
                for (int k0 = 0; k0 < IN; k0 += 1024) {
                    const int kc = min(1024, IN - k0);
                    __syncthreads();
                    for (int t = tid; t < nr * kc; t += NTHREADS) {
                        int r = t / kc, kk = t - r * kc;
                        xs[r][kk] = x[(size_t)(r0 + r) * IN + k0 + kk];
                    }
                    __syncthreads();
                    for (int o = tid; o < OUT; o += NTHREADS) {
                        float acc[ROWS_PB];
                        #pragma unroll
                        for (int r = 0; r < ROWS_PB; r++) acc[r] = 0.f;
                        const float* wrow = weight + (size_t)o * IN + k0;
                        for (int kk = 0; kk < kc; kk++) {
                            float wq = quant1(wrow[kk]);
                            if (wq != 0.f) {
                                #pragma unroll
                                for (int r = 0; r < ROWS_PB; r++)
                                    acc[r] += xs[r][kk] * wq;
                            }
                        }
                        for (int r = 0; r < nr; r++)
                            out[(size_t)(r0 + r) * OUT + o] += acc[r];
                    }
                }
            }
        }
    }

    // ---- global reset ticket: last-finishing block rearms for next replay.
    // Every fill block read g_nnz before arriving here; quant blocks done.
    __syncthreads();
    if (tid == 0) {
        unsigned t = atomicAdd(&g_done, 1u);
        if (t == (unsigned)NBLOCKS - 1u) {
            g_nnz = 0; g_qdone = 0u; g_ready = 0u; g_done = 0u;
        }
    }
}

extern "C" void kernel_launch(void* const* d_in, const int* in_sizes, int n_in,
                              void* d_out, int out_size) {
    const float* x      = (const float*)d_in[0];   // [B, IN]
    const float* weight = (const float*)d_in[1];   // [OUT, IN]
    const float* bias   = (const float*)d_in[2];   // [OUT]
    float* out = (float*)d_out;                    // [B, OUT]

    int OUT = in_sizes[2];
    int IN  = in_sizes[1] / OUT;
    int B   = in_sizes[0] / IN;

    // Role split ~ traffic ratio: W read 64 MB : out write 128 MB -> 1:2.
    const int QB = NBLOCKS / 3;                    // 197 quant, 395 fill

    k_fused<<<NBLOCKS, NTHREADS>>>(x, weight, bias, out, IN, OUT, B, QB);
}

// round 13
// speedup vs baseline: 1.3707x; 1.3707x over previous
#include <cuda_runtime.h>
#include <cuda_bf16.h>

// ---------------------------------------------------------------------------
// QuantizedLinear: out = x @ quantize(W)^T + bias
// quantize(w) = clamp(ceil(w - 0.5), -4, 3)  (== jnp argmin, first-index ties)
// W = randn*0.1 -> nonzero quantized entries need |w| >= 5 sigma -> nnz ~ 10.
//
// SINGLE kernel, 1184 blocks (8/SM via launch_bounds(256,8) => one wave):
//   quant blocks (bids 0..QB):  stream-read W (64 MB), collect nonzeros,
//                               signal g_ready. NEVER waits.
//   fill blocks  (bids QB..):   register-cached bias -> pure STG stream over
//                               owned 4-row chunks (overlaps quant's reads),
//                               spin on g_ready, then fix up OWN rows only
//                               (cache-warm, no cross-block races).
//   nnz > NNZ_CAP: fill blocks run owned-rows dense GEMM (safety net).
//   Last-finishing block resets counters for the next graph replay.
// R12 lesson: 592 blocks starved MLP (2.4 TB/s). 1184 blocks = R8's geometry
// which sustained 5.5 TB/s on the same mixed R/W streams.
// ---------------------------------------------------------------------------

#define NNZ_CAP (1 << 20)   // 1M entries = 8 MB scratch
#define ROWS_PB 4           // rows per fill chunk (64 KB contiguous stores)
#define NBLOCKS 1184        // 148 SMs * 8 blocks
#define NTHREADS 256

__device__ int                   g_nnz;      // zero-init; reset at end
__device__ unsigned int          g_qdone;    // quant-block completion ticket
__device__ volatile unsigned int g_ready;    // all nonzeros published
__device__ unsigned int          g_done;     // global reset ticket
__device__ unsigned int          g_eidx[NNZ_CAP];   // o*IN + i
__device__ float                 g_eval[NNZ_CAP];   // quantized level

__device__ __forceinline__ float quant1(float w) {
    float q = ceilf(w - 0.5f);               // round-half-down, exact vs argmin
    return fmaxf(-4.0f, fminf(3.0f, q));
}

__global__ void __launch_bounds__(NTHREADS, 8)
k_fused(const float* __restrict__ x,
        const float* __restrict__ weight,
        const float* __restrict__ bias,
        float* __restrict__ out,
        int IN, int OUT, int B, int QB) {
    const int tid = threadIdx.x;

    if ((int)blockIdx.x < QB) {
        // ================= QUANT ROLE: pure-read stream over W ==============
        const unsigned Wn = (unsigned)OUT * (unsigned)IN;
        const unsigned W4 = Wn >> 2;
        const unsigned gid = blockIdx.x * NTHREADS + tid;
        const unsigned stride = (unsigned)QB * NTHREADS;
        const float4* w4p = reinterpret_cast<const float4*>(weight);
        for (unsigned t = gid; t < W4; t += stride) {
            float4 w = __ldcs(&w4p[t]);      // streaming: no reuse
            float q0 = quant1(w.x), q1 = quant1(w.y);
            float q2 = quant1(w.z), q3 = quant1(w.w);
            if ((q0 != 0.f) | (q1 != 0.f) | (q2 != 0.f) | (q3 != 0.f)) {
                unsigned base = t << 2;
                if (q0 != 0.f) { int s = atomicAdd(&g_nnz, 1); if (s < NNZ_CAP) { g_eidx[s] = base + 0u; g_eval[s] = q0; } }
                if (q1 != 0.f) { int s = atomicAdd(&g_nnz, 1); if (s < NNZ_CAP) { g_eidx[s] = base + 1u; g_eval[s] = q1; } }
                if (q2 != 0.f) { int s = atomicAdd(&g_nnz, 1); if (s < NNZ_CAP) { g_eidx[s] = base + 2u; g_eval[s] = q2; } }
                if (q3 != 0.f) { int s = atomicAdd(&g_nnz, 1); if (s < NNZ_CAP) { g_eidx[s] = base + 3u; g_eval[s] = q3; } }
            }
        }
        unsigned tail = Wn & 3u;             // no-op for 4-divisible shapes
        if (gid < tail) {
            unsigned e = (W4 << 2) + gid;
            float q = quant1(weight[e]);
            if (q != 0.f) { int s = atomicAdd(&g_nnz, 1); if (s < NNZ_CAP) { g_eidx[s] = e; g_eval[s] = q; } }
        }
        __threadfence();                     // publish g_eidx/g_eval stores
        __syncthreads();
        if (tid == 0) {
            unsigned t = atomicAdd(&g_qdone, 1u);
            if (t == (unsigned)QB - 1u) atomicExch((unsigned int*)&g_ready, 1u);
        }
    } else {
        // ================= FILL ROLE: owned 4-row chunks ====================
        const int fb = blockIdx.x - QB;                 // fill-block id
        const int FB = NBLOCKS - QB;
        const int nchunks = (B + ROWS_PB - 1) / ROWS_PB;

        // ---- Phase A: bias fill (pure-store stream, bias in registers) ----
        const unsigned OUT4 = (unsigned)OUT >> 2;
        const int cpt = (int)(OUT4 / NTHREADS);         // float4 cols / thread
        const bool fast = ((OUT & 3) == 0) && (OUT4 % NTHREADS == 0) && cpt <= 4;
        if (fast) {
            float4 bc[4];
            const float4* b4 = reinterpret_cast<const float4*>(bias);
            #pragma unroll
            for (int c = 0; c < 4; c++)
                if (c < cpt) bc[c] = __ldg(&b4[tid + c * NTHREADS]);
            float4* o4 = reinterpret_cast<float4*>(out);
            for (int ch = fb; ch < nchunks; ch += FB) {
                const int r0 = ch * ROWS_PB;
                const int nr = min(ROWS_PB, B - r0);
                for (int r = 0; r < nr; r++) {
                    float4* row = o4 + (size_t)(r0 + r) * OUT4;
                    #pragma unroll
                    for (int c = 0; c < 4; c++)
                        if (c < cpt) __stcs(&row[tid + c * NTHREADS], bc[c]);
                }
            }
        } else {                                        // generic scalar path
            for (int ch = fb; ch < nchunks; ch += FB) {
                const int r0 = ch * ROWS_PB;
                const unsigned n = (unsigned)min(ROWS_PB, B - r0) * (unsigned)OUT;
                float* ob = out + (size_t)r0 * OUT;
                for (unsigned t = tid; t < n; t += NTHREADS)
                    ob[t] = __ldg(&bias[t % (unsigned)OUT]);
            }
        }
        __syncthreads();                    // fill stores ordered block-wide

        // ---- wait for quant side. Deadlock-free: quant never waits, and
        //      all QB quant blocks (lowest bids) are wave-1 resident even at
        //      worst-case 4 blocks/SM (592 >= QB). ----
        if (tid == 0) { while (g_ready == 0u) { } }
        __syncthreads();
        __threadfence();                    // acquire published entries
        const int nnz = *((volatile int*)&g_nnz);

        if (nnz <= NNZ_CAP) {
            // ---- Phase B: fixups on owned rows only (cache-warm lines) ----
            if (nnz > 0) {
                for (int ch = fb; ch < nchunks; ch += FB) {
                    const int r0 = ch * ROWS_PB;
                    const int nr = min(ROWS_PB, B - r0);
                    const int items = nnz * nr;
                    for (int t = tid; t < items; t += NTHREADS) {
                        const int e = t / nr;
                        const int r = t - e * nr;
                        const unsigned idx = __ldg(&g_eidx[e]);
                        const float v = __ldg(&g_eval[e]);
                        const unsigned o = idx / (unsigned)IN;  // shifts (pow2)
                        const unsigned i = idx % (unsigned)IN;
                        const int b = r0 + r;
                        atomicAdd(&out[(size_t)b * OUT + o],
                                  v * __ldg(&x[(size_t)b * IN + i]));
                    }
                }
            }
        } else {
            // ---- Dense safety net: owned-rows GEMM (never taken) ----
            __shared__ float xs[ROWS_PB][1024];
            for (int ch = fb; ch < nchunks; ch += FB) {
                const int r0 = ch * ROWS_PB;
                const int nr = min(ROWS_PB, B - r0);
                for (int k0 = 0; k0 < IN; k0 += 1024) {
                    const int kc = min(1024, IN - k0);
                    __syncthreads();
                    for (int t = tid; t < nr * kc; t += NTHREADS) {
                        int r = t / kc, kk = t - r * kc;
                        xs[r][kk] = x[(size_t)(r0 + r) * IN + k0 + kk];
                    }
                    __syncthreads();
                    for (int o = tid; o < OUT; o += NTHREADS) {
                        float acc[ROWS_PB];
                        #pragma unroll
                        for (int r = 0; r < ROWS_PB; r++) acc[r] = 0.f;
                        const float* wrow = weight + (size_t)o * IN + k0;
                        for (int kk = 0; kk < kc; kk++) {
                            float wq = quant1(wrow[kk]);
                            if (wq != 0.f) {
                                #pragma unroll
                                for (int r = 0; r < ROWS_PB; r++)
                                    acc[r] += xs[r][kk] * wq;
                            }
                        }
                        for (int r = 0; r < nr; r++)
                            out[(size_t)(r0 + r) * OUT + o] += acc[r];
                    }
                }
            }
        }
    }

    // ---- global reset ticket: last-finishing block rearms for next replay.
    __syncthreads();
    if (tid == 0) {
        unsigned t = atomicAdd(&g_done, 1u);
        if (t == (unsigned)NBLOCKS - 1u) {
            g_nnz = 0; g_qdone = 0u; g_ready = 0u; g_done = 0u;
        }
    }
}

extern "C" void kernel_launch(void* const* d_in, const int* in_sizes, int n_in,
                              void* d_out, int out_size) {
    const float* x      = (const float*)d_in[0];   // [B, IN]
    const float* weight = (const float*)d_in[1];   // [OUT, IN]
    const float* bias   = (const float*)d_in[2];   // [OUT]
    float* out = (float*)d_out;                    // [B, OUT]

    int OUT = in_sizes[2];
    int IN  = in_sizes[1] / OUT;
    int B   = in_sizes[0] / IN;

    // Role split ~ traffic ratio: W read 64 MB : out write 128 MB -> 1:2.
    const int QB = NBLOCKS / 3;                    // 395 quant, 789 fill

    k_fused<<<NBLOCKS, NTHREADS>>>(x, weight, bias, out, IN, OUT, B, QB);
}

// round 14
// speedup vs baseline: 2.0291x; 1.4803x over previous
#include <cuda_runtime.h>
#include <cuda_bf16.h>

// ---------------------------------------------------------------------------
// QuantizedLinear: out = x @ quantize(W)^T + bias
// quantize(w) = clamp(ceil(w - 0.5), -4, 3)  (== jnp argmin, first-index ties)
// W = randn*0.1 -> nonzero quantized entries need |w| >= 5 sigma -> nnz ~ 10.
//
// Proven two-kernel structure (R11 = 43.7us) + targeted fixes:
//   k_quant:    pure-read stream over W, 4x unrolled batched loads (MLP=4).
//   k_fill_fix: block owns 4 rows; bias cached in registers -> pure STG.128
//               fill stream; then fixups on own rows (cache-warm, no races).
//               nnz > NNZ_CAP: owned-rows dense GEMM safety net (never taken).
//               Last-finishing block resets the counter for the next replay.
// Overlap variants (R12: 75.8, R13: 55.3) are abandoned: mixed-role streams
// never summed; serial read-phase + write-phase is the reliable optimum.
// ---------------------------------------------------------------------------

#define NNZ_CAP (1 << 20)   // 1M entries = 8 MB scratch
#define ROWS_PB 4           // rows owned per k_fill_fix block

__device__ int          g_nnz;               // zero-init; reset by k_fill_fix
__device__ unsigned int g_done;              // ticket for last-block reset
__device__ unsigned int g_eidx[NNZ_CAP];     // o*IN + i
__device__ float        g_eval[NNZ_CAP];     // quantized level (nonzero)

__device__ __forceinline__ float quant1(float w) {
    float q = ceilf(w - 0.5f);               // round-half-down, exact vs argmin
    return fmaxf(-4.0f, fminf(3.0f, q));
}

__device__ __forceinline__ void collect4(float4 w, unsigned base) {
    float q0 = quant1(w.x), q1 = quant1(w.y);
    float q2 = quant1(w.z), q3 = quant1(w.w);
    if ((q0 != 0.f) | (q1 != 0.f) | (q2 != 0.f) | (q3 != 0.f)) {
        if (q0 != 0.f) { int s = atomicAdd(&g_nnz, 1); if (s < NNZ_CAP) { g_eidx[s] = base + 0u; g_eval[s] = q0; } }
        if (q1 != 0.f) { int s = atomicAdd(&g_nnz, 1); if (s < NNZ_CAP) { g_eidx[s] = base + 1u; g_eval[s] = q1; } }
        if (q2 != 0.f) { int s = atomicAdd(&g_nnz, 1); if (s < NNZ_CAP) { g_eidx[s] = base + 2u; g_eval[s] = q2; } }
        if (q3 != 0.f) { int s = atomicAdd(&g_nnz, 1); if (s < NNZ_CAP) { g_eidx[s] = base + 3u; g_eval[s] = q3; } }
    }
}

// ---- Kernel 1: pure-read quantize + collect, MLP=4 batched loads -----------
__global__ void __launch_bounds__(256, 8)
k_quant(const float* __restrict__ weight, int IN, int OUT) {
    const unsigned Wn = (unsigned)OUT * (unsigned)IN;
    const unsigned W4 = Wn >> 2;
    const unsigned gid = blockIdx.x * blockDim.x + threadIdx.x;
    const unsigned stride = gridDim.x * blockDim.x;
    const float4* w4p = reinterpret_cast<const float4*>(weight);

    unsigned t = gid;
    // 4 independent in-flight loads per iteration (latency hiding)
    for (; t + 3u * stride < W4; t += 4u * stride) {
        float4 a = __ldcs(&w4p[t]);
        float4 b = __ldcs(&w4p[t + stride]);
        float4 c = __ldcs(&w4p[t + 2u * stride]);
        float4 d = __ldcs(&w4p[t + 3u * stride]);
        collect4(a, t << 2);
        collect4(b, (t + stride) << 2);
        collect4(c, (t + 2u * stride) << 2);
        collect4(d, (t + 3u * stride) << 2);
    }
    for (; t < W4; t += stride)
        collect4(__ldcs(&w4p[t]), t << 2);

    unsigned tail = Wn & 3u;                 // no-op for 4-divisible shapes
    if (gid < tail) {
        unsigned e = (W4 << 2) + gid;
        float q = quant1(weight[e]);
        if (q != 0.f) { int s = atomicAdd(&g_nnz, 1); if (s < NNZ_CAP) { g_eidx[s] = e; g_eval[s] = q; } }
    }
}

// ---- Kernel 2: owned-rows fill (register bias, pure stores) + fixup --------
// grid = ceil(B / ROWS_PB), block = 256. Block b owns rows [b*R, b*R+R).
__global__ void __launch_bounds__(256, 8)
k_fill_fix(const float* __restrict__ x,
           const float* __restrict__ weight,
           const float* __restrict__ bias,
           float* __restrict__ out,
           int IN, int OUT, int B) {
    const int nnz = g_nnz;
    const int r0 = blockIdx.x * ROWS_PB;
    const int nrows = min(ROWS_PB, B - r0);
    const int tid = threadIdx.x;

    if (nnz <= NNZ_CAP) {
        // ---- Phase A: bias fill, bias cached in registers -> pure STG ----
        const unsigned OUT4 = (unsigned)OUT >> 2;
        const int cpt = (int)(OUT4 / 256u);            // float4 cols / thread
        const bool fast = (nrows == ROWS_PB) && ((OUT & 3) == 0) &&
                          (OUT4 % 256u == 0u) && (cpt >= 1) && (cpt <= 4);
        if (fast) {
            float4 bc[4];
            const float4* b4 = reinterpret_cast<const float4*>(bias);
            #pragma unroll
            for (int c = 0; c < 4; c++)
                if (c < cpt) bc[c] = __ldg(&b4[tid + c * 256]);
            float4* o4 = reinterpret_cast<float4*>(out) + (size_t)r0 * OUT4;
            #pragma unroll
            for (int r = 0; r < ROWS_PB; r++) {
                float4* row = o4 + (size_t)r * OUT4;
                #pragma unroll
                for (int c = 0; c < 4; c++)
                    if (c < cpt) __stcs(&row[tid + c * 256], bc[c]);
            }
        } else {                              // generic scalar path (tails)
            const unsigned n = (unsigned)nrows * (unsigned)OUT;
            float* ob = out + (size_t)r0 * OUT;
            for (unsigned t = tid; t < n; t += blockDim.x)
                ob[t] = __ldg(&bias[t % (unsigned)OUT]);
        }

        if (nnz > 0) {
            __syncthreads();   // order fill stores before fixup (block scope)

            // ---- Phase B: fixups for owned rows; lines are cache-warm ----
            const int items = nnz * nrows;
            for (int t = tid; t < items; t += blockDim.x) {
                const int e = t / nrows;
                const int r = t - e * nrows;
                const unsigned idx = __ldg(&g_eidx[e]);
                const float v = __ldg(&g_eval[e]);
                const unsigned o = idx / (unsigned)IN;   // shifts for pow2 IN
                const unsigned i = idx % (unsigned)IN;
                const int b = r0 + r;
                atomicAdd(&out[(size_t)b * OUT + o],
                          v * __ldg(&x[(size_t)b * IN + i]));
            }
        }
    } else {
        // ---- Dense safety net: owned-rows GEMM (never taken on dataset) ----
        __shared__ float xs[ROWS_PB][1024];
        {
            const unsigned n = (unsigned)nrows * (unsigned)OUT;
            float* ob = out + (size_t)r0 * OUT;
            for (unsigned t = tid; t < n; t += blockDim.x)
                ob[t] = __ldg(&bias[t % (unsigned)OUT]);
        }
        __syncthreads();
        for (int k0 = 0; k0 < IN; k0 += 1024) {
            const int kc = min(1024, IN - k0);
            for (int t = tid; t < nrows * kc; t += blockDim.x) {
                int r = t / kc, kk = t - r * kc;
                xs[r][kk] = x[(size_t)(r0 + r) * IN + k0 + kk];
            }
            __syncthreads();
            for (int o = tid; o < OUT; o += blockDim.x) {
                float acc[ROWS_PB];
                #pragma unroll
                for (int r = 0; r < ROWS_PB; r++) acc[r] = 0.f;
                const float* wrow = weight + (size_t)o * IN + k0;
                for (int kk = 0; kk < kc; kk++) {
                    float wq = quant1(wrow[kk]);
                    if (wq != 0.f) {
                        #pragma unroll
                        for (int r = 0; r < ROWS_PB; r++)
                            acc[r] += xs[r][kk] * wq;
                    }
                }
                for (int r = 0; r < nrows; r++)
                    out[(size_t)(r0 + r) * OUT + o] += acc[r];
            }
            __syncthreads();
        }
    }

    // Last-finishing block resets the counter for the next graph replay.
    // Every block read g_nnz before incrementing the ticket.
    __syncthreads();
    if (tid == 0) {
        unsigned t = atomicAdd(&g_done, 1u);
        if (t == gridDim.x - 1) { g_done = 0u; g_nnz = 0; }
    }
}

extern "C" void kernel_launch(void* const* d_in, const int* in_sizes, int n_in,
                              void* d_out, int out_size) {
    const float* x      = (const float*)d_in[0];   // [B, IN]
    const float* weight = (const float*)d_in[1];   // [OUT, IN]
    const float* bias   = (const float*)d_in[2];   // [OUT]
    float* out = (float*)d_out;                    // [B, OUT]

    int OUT = in_sizes[2];
    int IN  = in_sizes[1] / OUT;
    int B   = in_sizes[0] / IN;

    k_quant<<<1184, 256>>>(weight, IN, OUT);

    int fblocks = (B + ROWS_PB - 1) / ROWS_PB;     // 2048 for B=8192
    k_fill_fix<<<fblocks, 256>>>(x, weight, bias, out, IN, OUT, B);
}